// round 8
// baseline (speedup 1.0000x reference)
#include <cuda_runtime.h>
#include <cuda_fp16.h>
#include <cuda_fp8.h>
#include <cstdint>

// ============================================================================
// Plain sm_100 target: tcgen05/TMA unavailable. Path: cp.async + ldmatrix +
// mma.sync.m16n8k16 (fp16, f32 acc) with register fragment double-buffering
// so LDSM latency hides under HMMA execution (r7 showed them serializing:
// measured 418us == smem-phase 178us + mma-phase 239us exactly).
// ============================================================================

static constexpr int GK   = 2048;
static constexpr int GN   = 2048;
static constexpr int MAXM = 16384;

// Exact power-of-two pre-scales keep fp16 operands in the normal range.
static constexpr float A_SCALE   = 64.0f;
static constexpr float B_SCALE   = 1024.0f;
static constexpr float OUT_SCALE = 1.0f / 65536.0f;

__device__ __align__(128) __half g_xdq[(size_t)MAXM * GK];   // 64 MB
__device__ __align__(128) __half g_wdq[(size_t)GN * GK];     //  8 MB

#define SMEM_SWIZZLE_128B(byte_offset) \
    ((byte_offset) ^ (((byte_offset) >> 3) & 0x70))

__device__ __forceinline__ uint32_t smem_to_u32(const void* smem_ptr) {
    uint32_t addr;
    asm("{ .reg .u64 tmp; cvta.to.shared.u64 tmp, %1; cvt.u32.u64 %0, tmp; }"
        : "=r"(addr) : "l"(smem_ptr));
    return addr;
}

// ============================================================================
// Kernel 1: per-token-group fp8 quantize + dequantize x -> fp16 (x 2^6).
// One warp per TWO 128-element groups (ILP=2).
// ============================================================================
__global__ __launch_bounds__(256) void quant_x_kernel(
    const float* __restrict__ x, int npairs
) {
    int p = blockIdx.x * 8 + (threadIdx.x >> 5);
    if (p >= npairs) return;
    int lane = threadIdx.x & 31;
    size_t base = (size_t)p * 256;

    const float4 v0 = reinterpret_cast<const float4*>(x + base)[lane];
    const float4 v1 = reinterpret_cast<const float4*>(x + base + 128)[lane];

    float m0 = fmaxf(fmaxf(fabsf(v0.x), fabsf(v0.y)), fmaxf(fabsf(v0.z), fabsf(v0.w)));
    float m1 = fmaxf(fmaxf(fabsf(v1.x), fabsf(v1.y)), fmaxf(fabsf(v1.z), fabsf(v1.w)));
    #pragma unroll
    for (int o = 16; o > 0; o >>= 1) {
        m0 = fmaxf(m0, __shfl_xor_sync(0xffffffffu, m0, o));
        m1 = fmaxf(m1, __shfl_xor_sync(0xffffffffu, m1, o));
    }
    m0 = fmaxf(m0, 1e-12f);
    m1 = fmaxf(m1, 1e-12f);

    float s0 = 448.0f / m0, inv0 = (m0 / 448.0f) * A_SCALE;
    float s1 = 448.0f / m1, inv1 = (m1 / 448.0f) * A_SCALE;

    float r0[4] = {v0.x, v0.y, v0.z, v0.w};
    float r1[4] = {v1.x, v1.y, v1.z, v1.w};
    __half h0[4], h1[4];
    #pragma unroll
    for (int i = 0; i < 4; i++) {
        float q0 = fminf(fmaxf(r0[i] * s0, -448.0f), 448.0f);
        float q1 = fminf(fmaxf(r1[i] * s1, -448.0f), 448.0f);
        h0[i] = __float2half_rn(float(__nv_fp8_e4m3(q0)) * inv0);
        h1[i] = __float2half_rn(float(__nv_fp8_e4m3(q1)) * inv1);
    }
    __half2* dst = reinterpret_cast<__half2*>(g_xdq + base);
    dst[lane * 2]          = __halves2half2(h0[0], h0[1]);
    dst[lane * 2 + 1]      = __halves2half2(h0[2], h0[3]);
    dst[64 + lane * 2]     = __halves2half2(h1[0], h1[1]);
    dst[64 + lane * 2 + 1] = __halves2half2(h1[2], h1[3]);
}

// ============================================================================
// Kernel 2: weight dequant -> fp16 (x 2^10)
// ============================================================================
__global__ __launch_bounds__(256) void dequant_w_kernel(
    const float* __restrict__ w, const float* __restrict__ ws
) {
    int i = blockIdx.x * blockDim.x + threadIdx.x;
    if (i >= GN * GK / 4) return;
    float4 v = reinterpret_cast<const float4*>(w)[i];
    int base = i * 4;
    int n = base >> 11;
    int k = base & (GK - 1);
    float s = ws[((n >> 7) * (GK / 128)) + (k >> 7)] * B_SCALE;
    __half2* dst = reinterpret_cast<__half2*>(g_wdq);
    dst[i * 2]     = __halves2half2(__float2half_rn(v.x * s), __float2half_rn(v.y * s));
    dst[i * 2 + 1] = __halves2half2(__float2half_rn(v.z * s), __float2half_rn(v.w * s));
}

// ============================================================================
// Kernel 3: fp16 mma.sync GEMM. CTA 128x128, BK=64, 3-stage cp.async,
// 8 warps @ 64x32, double-buffered register fragments.
// ============================================================================
static constexpr int BM = 128;
static constexpr int BN = 128;
static constexpr int BK = 64;
static constexpr int STAGES = 3;

static constexpr int A_STAGE_B = BM * 128;
static constexpr int B_STAGE_B = BN * 128;
static constexpr int STAGE_B   = A_STAGE_B + B_STAGE_B;   // 32 KB
static constexpr int SMEM_TOTAL = STAGES * STAGE_B;        // 96 KB

__device__ __forceinline__ void cp16(uint32_t dst, const void* src) {
    asm volatile("cp.async.cg.shared.global [%0], [%1], 16;\n"
                 :: "r"(dst), "l"(src));
}

__device__ __forceinline__ void ldsm4(uint32_t& r0, uint32_t& r1,
                                      uint32_t& r2, uint32_t& r3, uint32_t addr) {
    asm volatile("ldmatrix.sync.aligned.m8n8.x4.shared.b16 {%0,%1,%2,%3}, [%4];"
                 : "=r"(r0), "=r"(r1), "=r"(r2), "=r"(r3) : "r"(addr));
}

__device__ __forceinline__ void mma16816(float* d,
                                         uint32_t a0, uint32_t a1, uint32_t a2, uint32_t a3,
                                         uint32_t b0, uint32_t b1) {
    asm volatile(
        "mma.sync.aligned.m16n8k16.row.col.f32.f16.f16.f32 "
        "{%0,%1,%2,%3}, {%4,%5,%6,%7}, {%8,%9}, {%0,%1,%2,%3};"
        : "+f"(d[0]), "+f"(d[1]), "+f"(d[2]), "+f"(d[3])
        : "r"(a0), "r"(a1), "r"(a2), "r"(a3), "r"(b0), "r"(b1));
}

__device__ __forceinline__ void load_stage(uint32_t sb, int slot,
                                           int m0, int n0, int k0, int tid) {
    uint32_t abase = sb + slot * STAGE_B;
    uint32_t bbase = abase + A_STAGE_B;
    const char* asrc = reinterpret_cast<const char*>(g_xdq + (size_t)m0 * GK + k0);
    const char* bsrc = reinterpret_cast<const char*>(g_wdq + (size_t)n0 * GK + k0);
    const size_t ROWB = GK * sizeof(__half);
    #pragma unroll
    for (int i = tid; i < (BM + BN) * 4; i += 256) {
        uint32_t base;
        const char* src;
        int row = (i >> 2) & 127;
        int c   = i & 3;
        if (i < BM * 4) { base = abase; src = asrc + (size_t)row * ROWB + c * 32; }
        else            { base = bbase; src = bsrc + (size_t)row * ROWB + c * 32; }
        uint32_t off = (uint32_t)(row * 128 + c * 32);
        cp16(base + SMEM_SWIZZLE_128B(off), src);
        cp16(base + SMEM_SWIZZLE_128B(off + 16), src + 16);
    }
    asm volatile("cp.async.commit_group;");
}

__global__ __launch_bounds__(256) void gemm_f16_kernel(
    const float* __restrict__ bias, float* __restrict__ out, int M
) {
    extern __shared__ char smem[];
    uint32_t sb = smem_to_u32(smem);
    int tid  = threadIdx.x;
    int wid  = tid >> 5;
    int lane = tid & 31;
    int wm = wid & 1;
    int wn = wid >> 1;
    int m0 = blockIdx.y * BM;
    int n0 = blockIdx.x * BN;

    int lrow = (lane & 7) + (((lane >> 3) & 1) << 3);
    int lc8  = ((lane >> 4) & 1) << 3;
    // Per-kk ldsm byte columns (pre-swizzle)
    int acol_base = (wm * 64 + lrow) * 128 + lc8 * 2;
    int bcol_base = (wn * 32 + lrow) * 128 + lc8 * 2;

    float acc[4][4][4];
    #pragma unroll
    for (int i = 0; i < 4; i++)
        #pragma unroll
        for (int j = 0; j < 4; j++)
            #pragma unroll
            for (int q = 0; q < 4; q++) acc[i][j][q] = 0.0f;

    const int KS = GK / BK;   // 32

    #pragma unroll
    for (int s = 0; s < STAGES - 1; s++)
        load_stage(sb, s, m0, n0, s * BK, tid);

    for (int ks = 0; ks < KS; ks++) {
        int slot = ks % STAGES;
        asm volatile("cp.async.wait_group %0;" :: "n"(STAGES - 2));
        __syncthreads();

        // Refill the retired slot immediately (safe: last read at iter ks-1,
        // all warps past the barrier above). Gets gmem loads in flight early.
        int nk = ks + STAGES - 1;
        if (nk < KS) {
            load_stage(sb, nk % STAGES, m0, n0, nk * BK, tid);
        } else {
            asm volatile("cp.async.commit_group;");
        }

        uint32_t abase = sb + slot * STAGE_B;
        uint32_t bbase = abase + A_STAGE_B;

        // Double-buffered fragments: ldsm(kk+1) issued before mma(kk).
        uint32_t a[2][4][4], b[2][2][4];

        // Preload kk = 0 into buffer 0
        #pragma unroll
        for (int mt = 0; mt < 4; mt++) {
            uint32_t off = (uint32_t)(acol_base + mt * 16 * 128);
            ldsm4(a[0][mt][0], a[0][mt][1], a[0][mt][2], a[0][mt][3],
                  abase + SMEM_SWIZZLE_128B(off));
        }
        #pragma unroll
        for (int bt = 0; bt < 2; bt++) {
            uint32_t off = (uint32_t)(bcol_base + bt * 16 * 128);
            ldsm4(b[0][bt][0], b[0][bt][1], b[0][bt][2], b[0][bt][3],
                  bbase + SMEM_SWIZZLE_128B(off));
        }

        #pragma unroll
        for (int kk = 0; kk < BK / 16; kk++) {
            int cur = kk & 1;
            int nxt = cur ^ 1;
            if (kk < BK / 16 - 1) {
                int kc = (kk + 1) * 32;   // byte column of next k-step
                #pragma unroll
                for (int mt = 0; mt < 4; mt++) {
                    uint32_t off = (uint32_t)(acol_base + mt * 16 * 128 + kc);
                    ldsm4(a[nxt][mt][0], a[nxt][mt][1], a[nxt][mt][2], a[nxt][mt][3],
                          abase + SMEM_SWIZZLE_128B(off));
                }
                #pragma unroll
                for (int bt = 0; bt < 2; bt++) {
                    uint32_t off = (uint32_t)(bcol_base + bt * 16 * 128 + kc);
                    ldsm4(b[nxt][bt][0], b[nxt][bt][1], b[nxt][bt][2], b[nxt][bt][3],
                          bbase + SMEM_SWIZZLE_128B(off));
                }
            }
            #pragma unroll
            for (int mt = 0; mt < 4; mt++) {
                #pragma unroll
                for (int bt = 0; bt < 2; bt++) {
                    mma16816(acc[mt][bt * 2 + 0],
                             a[cur][mt][0], a[cur][mt][1], a[cur][mt][2], a[cur][mt][3],
                             b[cur][bt][0], b[cur][bt][2]);
                    mma16816(acc[mt][bt * 2 + 1],
                             a[cur][mt][0], a[cur][mt][1], a[cur][mt][2], a[cur][mt][3],
                             b[cur][bt][1], b[cur][bt][3]);
                }
            }
        }
    }

    // Epilogue
    int qrow = lane >> 2;
    int qcol = (lane & 3) * 2;
    #pragma unroll
    for (int mt = 0; mt < 4; mt++) {
        int r0 = m0 + wm * 64 + mt * 16 + qrow;
        #pragma unroll
        for (int nt = 0; nt < 4; nt++) {
            int col = n0 + wn * 32 + (nt >> 1) * 16 + (nt & 1) * 8 + qcol;
            float b0 = bias[col], b1 = bias[col + 1];
            float2 v0, v1;
            v0.x = acc[mt][nt][0] * OUT_SCALE + b0;
            v0.y = acc[mt][nt][1] * OUT_SCALE + b1;
            v1.x = acc[mt][nt][2] * OUT_SCALE + b0;
            v1.y = acc[mt][nt][3] * OUT_SCALE + b1;
            *reinterpret_cast<float2*>(out + (size_t)r0 * GN + col) = v0;
            *reinterpret_cast<float2*>(out + (size_t)(r0 + 8) * GN + col) = v1;
        }
    }
}

// ============================================================================
// Launch
// ============================================================================
extern "C" void kernel_launch(void* const* d_in, const int* in_sizes, int n_in,
                              void* d_out, int out_size) {
    const float* x    = (const float*)d_in[0];
    const float* w    = (const float*)d_in[1];
    const float* ws   = (const float*)d_in[2];
    const float* bias = (const float*)d_in[3];
    float* out = (float*)d_out;

    int O = in_sizes[3];
    int H = in_sizes[1] / O;
    int M = in_sizes[0] / H;
    int npairs = M * (H / 128) / 2;

    quant_x_kernel<<<(npairs + 7) / 8, 256>>>(x, npairs);
    dequant_w_kernel<<<(O * H / 4 + 255) / 256, 256>>>(w, ws);

    cudaFuncSetAttribute(gemm_f16_kernel,
                         cudaFuncAttributeMaxDynamicSharedMemorySize, SMEM_TOTAL);
    dim3 grid(GN / BN, M / BM);
    gemm_f16_kernel<<<grid, 256, SMEM_TOTAL>>>(bias, out, M);
}

// round 11
// speedup vs baseline: 1.0441x; 1.0441x over previous
#include <cuda_runtime.h>
#include <cuda_fp16.h>
#include <cuda_fp8.h>
#include <cstdint>

// ============================================================================
// Plain sm_100 target: tcgen05/TMA unavailable. Path: cp.async + ldmatrix +
// mma.sync.m16n8k16 (fp16, f32 acc).
// R7/R8: CTA 128x128 -> smem traffic == MMA budget (1024/1024 cyc per stage),
// no overlap slack, ~420us. Fix: CTA 128x256 -> 1408 vs 2048 cyc.
// R9/R10 (8 warps @ 64x64, ~200 regs) died without feedback; this variant
// keeps the ratio with 16 warps @ 64x32 (R7-proven structure, ~130 regs).
// ============================================================================

static constexpr int GK   = 2048;
static constexpr int GN   = 2048;
static constexpr int MAXM = 16384;

// Exact power-of-two pre-scales keep fp16 operands in the normal range.
static constexpr float A_SCALE   = 64.0f;
static constexpr float B_SCALE   = 1024.0f;
static constexpr float OUT_SCALE = 1.0f / 65536.0f;

__device__ __align__(128) __half g_xdq[(size_t)MAXM * GK];   // 64 MB
__device__ __align__(128) __half g_wdq[(size_t)GN * GK];     //  8 MB

#define SMEM_SWIZZLE_128B(byte_offset) \
    ((byte_offset) ^ (((byte_offset) >> 3) & 0x70))

__device__ __forceinline__ uint32_t smem_to_u32(const void* smem_ptr) {
    uint32_t addr;
    asm("{ .reg .u64 tmp; cvta.to.shared.u64 tmp, %1; cvt.u32.u64 %0, tmp; }"
        : "=r"(addr) : "l"(smem_ptr));
    return addr;
}

// ============================================================================
// Kernel 1: per-token-group fp8 quantize + dequantize x -> fp16 (x 2^6).
// One warp per TWO 128-element groups (ILP=2).
// ============================================================================
__global__ __launch_bounds__(256) void quant_x_kernel(
    const float* __restrict__ x, int npairs
) {
    int p = blockIdx.x * 8 + (threadIdx.x >> 5);
    if (p >= npairs) return;
    int lane = threadIdx.x & 31;
    size_t base = (size_t)p * 256;

    const float4 v0 = reinterpret_cast<const float4*>(x + base)[lane];
    const float4 v1 = reinterpret_cast<const float4*>(x + base + 128)[lane];

    float m0 = fmaxf(fmaxf(fabsf(v0.x), fabsf(v0.y)), fmaxf(fabsf(v0.z), fabsf(v0.w)));
    float m1 = fmaxf(fmaxf(fabsf(v1.x), fabsf(v1.y)), fmaxf(fabsf(v1.z), fabsf(v1.w)));
    #pragma unroll
    for (int o = 16; o > 0; o >>= 1) {
        m0 = fmaxf(m0, __shfl_xor_sync(0xffffffffu, m0, o));
        m1 = fmaxf(m1, __shfl_xor_sync(0xffffffffu, m1, o));
    }
    m0 = fmaxf(m0, 1e-12f);
    m1 = fmaxf(m1, 1e-12f);

    float s0 = 448.0f / m0, inv0 = (m0 / 448.0f) * A_SCALE;
    float s1 = 448.0f / m1, inv1 = (m1 / 448.0f) * A_SCALE;

    float r0[4] = {v0.x, v0.y, v0.z, v0.w};
    float r1[4] = {v1.x, v1.y, v1.z, v1.w};
    __half h0[4], h1[4];
    #pragma unroll
    for (int i = 0; i < 4; i++) {
        float q0 = fminf(fmaxf(r0[i] * s0, -448.0f), 448.0f);
        float q1 = fminf(fmaxf(r1[i] * s1, -448.0f), 448.0f);
        h0[i] = __float2half_rn(float(__nv_fp8_e4m3(q0)) * inv0);
        h1[i] = __float2half_rn(float(__nv_fp8_e4m3(q1)) * inv1);
    }
    __half2* dst = reinterpret_cast<__half2*>(g_xdq + base);
    dst[lane * 2]          = __halves2half2(h0[0], h0[1]);
    dst[lane * 2 + 1]      = __halves2half2(h0[2], h0[3]);
    dst[64 + lane * 2]     = __halves2half2(h1[0], h1[1]);
    dst[64 + lane * 2 + 1] = __halves2half2(h1[2], h1[3]);
}

// ============================================================================
// Kernel 2: weight dequant -> fp16 (x 2^10)
// ============================================================================
__global__ __launch_bounds__(256) void dequant_w_kernel(
    const float* __restrict__ w, const float* __restrict__ ws
) {
    int i = blockIdx.x * blockDim.x + threadIdx.x;
    if (i >= GN * GK / 4) return;
    float4 v = reinterpret_cast<const float4*>(w)[i];
    int base = i * 4;
    int n = base >> 11;
    int k = base & (GK - 1);
    float s = ws[((n >> 7) * (GK / 128)) + (k >> 7)] * B_SCALE;
    __half2* dst = reinterpret_cast<__half2*>(g_wdq);
    dst[i * 2]     = __halves2half2(__float2half_rn(v.x * s), __float2half_rn(v.y * s));
    dst[i * 2 + 1] = __halves2half2(__float2half_rn(v.z * s), __float2half_rn(v.w * s));
}

// ============================================================================
// Kernel 3: fp16 mma.sync GEMM. CTA 128x256, BK=64, 3-stage cp.async,
// 16 warps (512 threads) @ 64x32 warp tile.
// ============================================================================
static constexpr int BM = 128;
static constexpr int BN = 256;
static constexpr int BK = 64;
static constexpr int STAGES = 3;
static constexpr int NTHREADS = 512;

static constexpr int A_STAGE_B = BM * 128;                 // 16 KB
static constexpr int B_STAGE_B = BN * 128;                 // 32 KB
static constexpr int STAGE_B   = A_STAGE_B + B_STAGE_B;    // 48 KB
static constexpr int SMEM_TOTAL = STAGES * STAGE_B;        // 144 KB

__device__ __forceinline__ void cp16(uint32_t dst, const void* src) {
    asm volatile("cp.async.cg.shared.global [%0], [%1], 16;\n"
                 :: "r"(dst), "l"(src));
}

__device__ __forceinline__ void ldsm4(uint32_t& r0, uint32_t& r1,
                                      uint32_t& r2, uint32_t& r3, uint32_t addr) {
    asm volatile("ldmatrix.sync.aligned.m8n8.x4.shared.b16 {%0,%1,%2,%3}, [%4];"
                 : "=r"(r0), "=r"(r1), "=r"(r2), "=r"(r3) : "r"(addr));
}

__device__ __forceinline__ void mma16816(float* d,
                                         uint32_t a0, uint32_t a1, uint32_t a2, uint32_t a3,
                                         uint32_t b0, uint32_t b1) {
    asm volatile(
        "mma.sync.aligned.m16n8k16.row.col.f32.f16.f16.f32 "
        "{%0,%1,%2,%3}, {%4,%5,%6,%7}, {%8,%9}, {%0,%1,%2,%3};"
        : "+f"(d[0]), "+f"(d[1]), "+f"(d[2]), "+f"(d[3])
        : "r"(a0), "r"(a1), "r"(a2), "r"(a3), "r"(b0), "r"(b1));
}

__device__ __forceinline__ void load_stage(uint32_t sb, int slot,
                                           int m0, int n0, int k0, int tid) {
    uint32_t abase = sb + slot * STAGE_B;
    uint32_t bbase = abase + A_STAGE_B;
    const char* asrc = reinterpret_cast<const char*>(g_xdq + (size_t)m0 * GK + k0);
    const char* bsrc = reinterpret_cast<const char*>(g_wdq + (size_t)n0 * GK + k0);
    const size_t ROWB = GK * sizeof(__half);   // 4096 B
    // (BM + BN) rows x 8 chunks of 16B = 3072 ops, 6 per thread.
    #pragma unroll
    for (int i = tid; i < (BM + BN) * 8; i += NTHREADS) {
        uint32_t base;
        const char* src;
        int row, c = i & 7;
        if (i < BM * 8) {
            row = i >> 3;
            base = abase; src = asrc + (size_t)row * ROWB + c * 16;
        } else {
            row = (i - BM * 8) >> 3;
            base = bbase; src = bsrc + (size_t)row * ROWB + c * 16;
        }
        uint32_t off = (uint32_t)(row * 128 + c * 16);
        cp16(base + SMEM_SWIZZLE_128B(off), src);
    }
    asm volatile("cp.async.commit_group;");
}

__global__ __launch_bounds__(NTHREADS) void gemm_f16_kernel(
    const float* __restrict__ bias, float* __restrict__ out, int M
) {
    extern __shared__ char smem[];
    uint32_t sb = smem_to_u32(smem);
    int tid  = threadIdx.x;
    int wid  = tid >> 5;       // 0..15
    int lane = tid & 31;
    int wm = wid & 1;          // 0..1 -> 64-row slab
    int wn = wid >> 1;         // 0..7 -> 32-col slab
    int m0 = blockIdx.y * BM;
    int n0 = blockIdx.x * BN;

    int lrow = (lane & 7) + (((lane >> 3) & 1) << 3);
    int lc8  = ((lane >> 4) & 1) << 3;
    int acol_base = (wm * 64 + lrow) * 128 + lc8 * 2;
    int bcol_base = (wn * 32 + lrow) * 128 + lc8 * 2;

    float acc[4][4][4];    // [mt][nt(n8 within 32)][4]
    #pragma unroll
    for (int i = 0; i < 4; i++)
        #pragma unroll
        for (int j = 0; j < 4; j++)
            #pragma unroll
            for (int q = 0; q < 4; q++) acc[i][j][q] = 0.0f;

    const int KS = GK / BK;   // 32

    #pragma unroll
    for (int s = 0; s < STAGES - 1; s++)
        load_stage(sb, s, m0, n0, s * BK, tid);

    for (int ks = 0; ks < KS; ks++) {
        int slot = ks % STAGES;
        asm volatile("cp.async.wait_group %0;" :: "n"(STAGES - 2));
        __syncthreads();

        // Refill the retired slot immediately (safe: last read at iter ks-1).
        int nk = ks + STAGES - 1;
        if (nk < KS) {
            load_stage(sb, nk % STAGES, m0, n0, nk * BK, tid);
        } else {
            asm volatile("cp.async.commit_group;");
        }

        uint32_t abase = sb + slot * STAGE_B;
        uint32_t bbase = abase + A_STAGE_B;

        #pragma unroll
        for (int kk = 0; kk < BK / 16; kk++) {
            int kc = kk * 32;   // byte column of this k-step
            uint32_t a[4][4];
            #pragma unroll
            for (int mt = 0; mt < 4; mt++) {
                uint32_t off = (uint32_t)(acol_base + mt * 16 * 128 + kc);
                ldsm4(a[mt][0], a[mt][1], a[mt][2], a[mt][3],
                      abase + SMEM_SWIZZLE_128B(off));
            }
            uint32_t b[2][4];
            #pragma unroll
            for (int bt = 0; bt < 2; bt++) {
                uint32_t off = (uint32_t)(bcol_base + bt * 16 * 128 + kc);
                ldsm4(b[bt][0], b[bt][1], b[bt][2], b[bt][3],
                      bbase + SMEM_SWIZZLE_128B(off));
            }
            #pragma unroll
            for (int mt = 0; mt < 4; mt++) {
                #pragma unroll
                for (int bt = 0; bt < 2; bt++) {
                    mma16816(acc[mt][bt * 2 + 0],
                             a[mt][0], a[mt][1], a[mt][2], a[mt][3],
                             b[bt][0], b[bt][2]);      // n rows 0-7
                    mma16816(acc[mt][bt * 2 + 1],
                             a[mt][0], a[mt][1], a[mt][2], a[mt][3],
                             b[bt][1], b[bt][3]);      // n rows 8-15
                }
            }
        }
    }

    // Epilogue: scale + bias, f32 output
    int qrow = lane >> 2;
    int qcol = (lane & 3) * 2;
    #pragma unroll
    for (int mt = 0; mt < 4; mt++) {
        int r0 = m0 + wm * 64 + mt * 16 + qrow;
        #pragma unroll
        for (int nt = 0; nt < 4; nt++) {
            int col = n0 + wn * 32 + (nt >> 1) * 16 + (nt & 1) * 8 + qcol;
            float b0 = bias[col], b1 = bias[col + 1];
            float2 v0, v1;
            v0.x = acc[mt][nt][0] * OUT_SCALE + b0;
            v0.y = acc[mt][nt][1] * OUT_SCALE + b1;
            v1.x = acc[mt][nt][2] * OUT_SCALE + b0;
            v1.y = acc[mt][nt][3] * OUT_SCALE + b1;
            *reinterpret_cast<float2*>(out + (size_t)r0 * GN + col) = v0;
            *reinterpret_cast<float2*>(out + (size_t)(r0 + 8) * GN + col) = v1;
        }
    }
}

// ============================================================================
// Launch
// ============================================================================
extern "C" void kernel_launch(void* const* d_in, const int* in_sizes, int n_in,
                              void* d_out, int out_size) {
    const float* x    = (const float*)d_in[0];
    const float* w    = (const float*)d_in[1];
    const float* ws   = (const float*)d_in[2];
    const float* bias = (const float*)d_in[3];
    float* out = (float*)d_out;

    int O = in_sizes[3];
    int H = in_sizes[1] / O;
    int M = in_sizes[0] / H;
    int npairs = M * (H / 128) / 2;

    quant_x_kernel<<<(npairs + 7) / 8, 256>>>(x, npairs);
    dequant_w_kernel<<<(O * H / 4 + 255) / 256, 256>>>(w, ws);

    cudaFuncSetAttribute(gemm_f16_kernel,
                         cudaFuncAttributeMaxDynamicSharedMemorySize, SMEM_TOTAL);
    dim3 grid(GN / BN, M / BM);        // (8, 128)
    gemm_f16_kernel<<<grid, NTHREADS, SMEM_TOTAL>>>(bias, out, M);
}